// round 15
// baseline (speedup 1.0000x reference)
#include <cuda_runtime.h>
#include <cstdint>

// AnchorLoss: sum over masked pairs of 1 - exp(-||p_i - p_j||^2 / 10),
// p = embedding + abs_coords, B=8, N=2048, D=2.
//
// R12 shape (resubmitted after infra failure): identical math/loads to the
// measured-best R1 shape (transposed float2 point cache, __ldcs int4 masks,
// I2F+FFMA gating), but the j-dim is split in QUARTERS so blocks last ~5us
// instead of ~20us -> 6.9 generations/SM instead of 1.7, shrinking the
// wave-quantization tail.

constexpr int BDIM = 8;
constexpr int NDIM = 2048;
constexpr int JQ   = 512;               // j per block (quarter row)
constexpr int NJ   = NDIM / JQ;         // 4 j-quarters
constexpr int ROWS = 8;                 // i-rows per block (one warp per row)
constexpr int THREADS = ROWS * 32;      // 256
constexpr int GRID_X = NDIM / ROWS;     // 256
constexpr int NBLOCKS = GRID_X * NJ * BDIM;  // 8192
constexpr int Q = JQ / 4;               // 128 (transposed stride)
constexpr int NITER = JQ / 128;         // 4 iterations per warp

__device__ float g_partial[NBLOCKS];

__device__ __forceinline__ float ex2_approx(float x) {
    float r;
    asm("ex2.approx.ftz.f32 %0, %1;" : "=f"(r) : "f"(x));
    return r;
}

__global__ void __launch_bounds__(THREADS, 8)
anchor_main(const float* __restrict__ emb,
            const float* __restrict__ coords,
            const int*   __restrict__ mask) {
    // Transposed point cache for this j-quarter: sp[(t&3)*Q + (t>>2)] = p[j0+t]
    __shared__ float2 sp[JQ];
    __shared__ float wsum[ROWS];

    const int b  = blockIdx.z;
    const int j0 = blockIdx.y * JQ;
    const float2* e2 = reinterpret_cast<const float2*>(emb    + (size_t)b * NDIM * 2);
    const float2* c2 = reinterpret_cast<const float2*>(coords + (size_t)b * NDIM * 2);

    for (int t = threadIdx.x; t < JQ; t += THREADS) {
        float2 e = e2[j0 + t];
        float2 c = c2[j0 + t];
        sp[(t & 3) * Q + (t >> 2)] = make_float2(e.x + c.x, e.y + c.y);
    }
    __syncthreads();

    const int warp = threadIdx.x >> 5;
    const int lane = threadIdx.x & 31;
    const int i = blockIdx.x * ROWS + warp;

    // row-i point (L2-hit broadcast load)
    const float2 ei = e2[i], ci = c2[i];
    const float pix = ei.x + ci.x, piy = ei.y + ci.y;
    const float2 pi = make_float2(pix, piy);

    const int4* mrow = reinterpret_cast<const int4*>(
        mask + ((size_t)b * NDIM + (size_t)i) * NDIM + j0);

    constexpr float NEGC = -0.14426950408889634f;  // -log2(e)/TEMPERATURE

    float accE = 0.0f;  // sum of m * exp(...)
    int   cnt  = 0;     // count of m==1

#pragma unroll
    for (int it = 0; it < NITER; ++it) {   // 4 iterations (fully unrolled)
        const int a = it * 32 + lane;      // int4 index == transposed index
        const int4 m = __ldcs(&mrow[a]);   // masks for j = j0+4a .. j0+4a+3

        const float2 p0 = sp[0 * Q + a];
        const float2 p1 = sp[1 * Q + a];
        const float2 p2 = sp[2 * Q + a];
        const float2 p3 = sp[3 * Q + a];

        {
            float dx = pi.x - p0.x, dy = pi.y - p0.y;
            float arg = fmaf(dy, dy, dx * dx) * NEGC;
            accE = fmaf((float)m.x, ex2_approx(arg), accE);
            cnt += m.x;
        }
        {
            float dx = pi.x - p1.x, dy = pi.y - p1.y;
            float arg = fmaf(dy, dy, dx * dx) * NEGC;
            accE = fmaf((float)m.y, ex2_approx(arg), accE);
            cnt += m.y;
        }
        {
            float dx = pi.x - p2.x, dy = pi.y - p2.y;
            float arg = fmaf(dy, dy, dx * dx) * NEGC;
            accE = fmaf((float)m.z, ex2_approx(arg), accE);
            cnt += m.z;
        }
        {
            float dx = pi.x - p3.x, dy = pi.y - p3.y;
            float arg = fmaf(dy, dy, dx * dx) * NEGC;
            accE = fmaf((float)m.w, ex2_approx(arg), accE);
            cnt += m.w;
        }
    }

    float val = (float)cnt - accE;

    // warp reduce
#pragma unroll
    for (int off = 16; off; off >>= 1)
        val += __shfl_xor_sync(0xffffffffu, val, off);

    if (lane == 0) wsum[warp] = val;
    __syncthreads();

    if (threadIdx.x == 0) {
        float s = 0.0f;
#pragma unroll
        for (int w = 0; w < ROWS; ++w) s += wsum[w];
        g_partial[((size_t)blockIdx.z * NJ + blockIdx.y) * GRID_X + blockIdx.x] = s;
    }
}

// 1024 threads, one block: 8 partials each (independent loads), then
// deterministic double-precision shfl + smem tree.
__global__ void __launch_bounds__(1024)
anchor_reduce(float* __restrict__ out) {
    __shared__ double s[32];
    const int t    = threadIdx.x;
    const int lane = t & 31;
    const int warp = t >> 5;

    double acc = 0.0;
#pragma unroll
    for (int k = 0; k < NBLOCKS / 1024; ++k)
        acc += (double)g_partial[k * 1024 + t];

#pragma unroll
    for (int off = 16; off; off >>= 1)
        acc += __shfl_xor_sync(0xffffffffu, acc, off);

    if (lane == 0) s[warp] = acc;
    __syncthreads();

    if (warp == 0) {
        double v = s[lane];
#pragma unroll
        for (int off = 16; off; off >>= 1)
            v += __shfl_xor_sync(0xffffffffu, v, off);
        if (lane == 0) out[0] = (float)v;
    }
}

extern "C" void kernel_launch(void* const* d_in, const int* in_sizes, int n_in,
                              void* d_out, int out_size) {
    const float* emb    = (const float*)d_in[0];
    const float* coords = (const float*)d_in[1];
    const int*   mask   = (const int*)d_in[2];
    float* out = (float*)d_out;

    dim3 grid(GRID_X, NJ, BDIM);
    anchor_main<<<grid, THREADS>>>(emb, coords, mask);
    anchor_reduce<<<1, 1024>>>(out);
}